// round 7
// baseline (speedup 1.0000x reference)
#include <cuda_runtime.h>
#include <cstdint>
#include <cstddef>

// ---------------------------------------------------------------------------
// SNN forward:
//   cur1 = data @ w1^T + b1      -- fp32 SIMT GEMM (round-1 verbatim numerics)
//   pack[b,i] = 8 spike bits     -- elementwise LIF1 (beta1 = 1.0)
//   tail kernel (per batch row b):
//       compact nonzero pattern bytes -> active list (~41% density);
//       per active i: ONE LDG.128 of 4 w2t columns + 8 predicated
//       add.rn.f32x2 (bit t of pattern) -- no LUT, no smem traffic;
//       LIF2 + dot(w3) + mean fused in-register -> out[b]
//   R6 ncu: tail was L1-wavefront-bound (96.5%) on the 8x LDS.64 LUT reads.
//   Predicated add == add of 0.0 in RN fp32 -> bit-identical numerics.
// ---------------------------------------------------------------------------

static constexpr int BB  = 16384;
static constexpr int DIN = 512;
static constexpr int H0  = 1024;
static constexpr int H1  = 512;
static constexpr int T   = 8;

// Scratch (device globals -- no runtime allocation allowed)
__device__ __align__(256) unsigned char g_pack[(size_t)BB * H0];  // 16 MB
__device__ __align__(256) float         g_w2t [(size_t)H0 * H1]; //  2 MB
__device__ __align__(256) float         g_cur1[(size_t)BB * H0]; // 64 MB

// ===========================================================================
// GEMM1: round-1 fp32 SIMT SGEMM (verbatim -- known-good numerics).
// ===========================================================================
__global__ void __launch_bounds__(256) sgemm1_kernel(
    const float* __restrict__ A,
    const float* __restrict__ W,
    const float* __restrict__ bias,
    float* __restrict__ C,
    int M, int N, int K)
{
    __shared__ float As[16][128];
    __shared__ float Bs[16][128];

    const int tx = threadIdx.x;
    const int tm = tx >> 4;
    const int tn = tx & 15;

    const int m0 = blockIdx.y * 128;
    const int n0 = blockIdx.x * 128;

    float acc[8][8];
#pragma unroll
    for (int i = 0; i < 8; ++i)
#pragma unroll
        for (int j = 0; j < 8; ++j) acc[i][j] = 0.0f;

    for (int kt = 0; kt < K; kt += 16) {
#pragma unroll
        for (int s = 0; s < 2; ++s) {
            const int f  = tx + s * 256;
            const int r  = f >> 2;
            const int c4 = (f & 3) * 4;
            const int gk = kt + c4;
            {
                const int gm = m0 + r;
                float4 v = *reinterpret_cast<const float4*>(&A[(size_t)gm * K + gk]);
                As[c4 + 0][r] = v.x;
                As[c4 + 1][r] = v.y;
                As[c4 + 2][r] = v.z;
                As[c4 + 3][r] = v.w;
            }
            {
                const int gn = n0 + r;
                const float4 w = *reinterpret_cast<const float4*>(&W[(size_t)gn * K + gk]);
                Bs[c4 + 0][r] = w.x;
                Bs[c4 + 1][r] = w.y;
                Bs[c4 + 2][r] = w.z;
                Bs[c4 + 3][r] = w.w;
            }
        }
        __syncthreads();

#pragma unroll
        for (int k = 0; k < 16; ++k) {
            float a[8], b[8];
            *reinterpret_cast<float4*>(&a[0]) =
                *reinterpret_cast<const float4*>(&As[k][tm * 8]);
            *reinterpret_cast<float4*>(&a[4]) =
                *reinterpret_cast<const float4*>(&As[k][tm * 8 + 4]);
            *reinterpret_cast<float4*>(&b[0]) =
                *reinterpret_cast<const float4*>(&Bs[k][tn * 8]);
            *reinterpret_cast<float4*>(&b[4]) =
                *reinterpret_cast<const float4*>(&Bs[k][tn * 8 + 4]);
#pragma unroll
            for (int i = 0; i < 8; ++i)
#pragma unroll
                for (int j = 0; j < 8; ++j)
                    acc[i][j] = fmaf(a[i], b[j], acc[i][j]);
        }
        __syncthreads();
    }

    float bj[8];
    const int gn0 = n0 + tn * 8;
#pragma unroll
    for (int j = 0; j < 8; ++j) bj[j] = __ldg(&bias[gn0 + j]);

#pragma unroll
    for (int i = 0; i < 8; ++i) {
        const int gm = m0 + tm * 8 + i;
        float4 o0, o1;
        o0.x = acc[i][0] + bj[0];
        o0.y = acc[i][1] + bj[1];
        o0.z = acc[i][2] + bj[2];
        o0.w = acc[i][3] + bj[3];
        o1.x = acc[i][4] + bj[4];
        o1.y = acc[i][5] + bj[5];
        o1.z = acc[i][6] + bj[6];
        o1.w = acc[i][7] + bj[7];
        *reinterpret_cast<float4*>(&C[(size_t)gm * N + gn0])     = o0;
        *reinterpret_cast<float4*>(&C[(size_t)gm * N + gn0 + 4]) = o1;
    }
}

// ===========================================================================
// LIF layer 1 (beta1 = 1.0): 8 spike bits packed into one byte per (b,i)
// ===========================================================================
__global__ void spike_pack_kernel(const float* __restrict__ cur1,
                                  unsigned char* __restrict__ pack)
{
    const size_t i = (size_t)blockIdx.x * blockDim.x + threadIdx.x;
    if (i >= (size_t)BB * H0) return;
    const float c = cur1[i];
    float mem = 0.0f;
    unsigned p = 0;
#pragma unroll
    for (int t = 0; t < T; ++t) {
        const float reset = (mem > 1.0f) ? 1.0f : 0.0f;   // OLD mem
        mem = mem + c - reset;                             // beta1 = 1.0
        p |= ((mem - 1.0f) > 0.0f ? 1u : 0u) << t;
    }
    pack[i] = (unsigned char)p;
}

// ===========================================================================
// Transpose w2 [H1][H0] -> w2t [H0][H1]
// ===========================================================================
__global__ void transpose_w2_kernel(const float* __restrict__ w2,
                                    float* __restrict__ w2t)
{
    __shared__ float tile[32][33];
    const int bx = blockIdx.x * 32;
    const int by = blockIdx.y * 32;
    const int tx = threadIdx.x, ty = threadIdx.y;
#pragma unroll
    for (int j = 0; j < 32; j += 8)
        tile[ty + j][tx] = w2[(size_t)(by + ty + j) * H0 + bx + tx];
    __syncthreads();
#pragma unroll
    for (int j = 0; j < 32; j += 8)
        w2t[(size_t)(bx + ty + j) * H1 + by + tx] = tile[tx][ty + j];
}

// ===========================================================================
// Fused tail v2: 128 threads, thread owns 4 consecutive n (n0 = tid*4).
//   1) compact nonzero pattern bytes (ascending i, deterministic)
//   2) per active i: LDG.128 w2t row slice; 8x { setp on bit t;
//      @q add.rn.f32x2 x2 }  -- register-only, schedulable, no LUT
//   3) LIF2 + w3-dot in-register, block reduce -> out[b]
// ===========================================================================
__global__ void __launch_bounds__(128) snn_tail_kernel(
    const unsigned char* __restrict__ pack,   // [BB][H0]
    const float* __restrict__ w2t,            // [H0][H1]
    const float* __restrict__ b2,
    const float* __restrict__ w3,
    const float* __restrict__ b3,
    float* __restrict__ out)
{
    __shared__ uint32_t s_list[H0];
    __shared__ int   s_warp[4];
    __shared__ int   s_len;
    __shared__ float s_red[4];

    const int b    = blockIdx.x;
    const int tid  = threadIdx.x;
    const int lane = tid & 31;
    const int wid  = tid >> 5;

    // ---- compact nonzero pattern bytes (thread owns 8 bytes) ----
    const uint2 wd =
        reinterpret_cast<const uint2*>(pack)[(size_t)b * (H0 / 8) + tid];
    uint32_t bytes[8];
    int cnt = 0;
#pragma unroll
    for (int j = 0; j < 4; ++j) {
        bytes[j]     = (wd.x >> (8 * j)) & 255u;
        bytes[4 + j] = (wd.y >> (8 * j)) & 255u;
    }
#pragma unroll
    for (int j = 0; j < 8; ++j) cnt += (bytes[j] != 0u);

    int pre = cnt;
#pragma unroll
    for (int d = 1; d < 32; d <<= 1) {
        const int v = __shfl_up_sync(0xFFFFFFFFu, pre, d);
        if (lane >= d) pre += v;
    }
    const int wtot = __shfl_sync(0xFFFFFFFFu, pre, 31);
    const int excl = pre - cnt;
    if (lane == 31) s_warp[wid] = wtot;
    __syncthreads();
    if (tid == 0) {
        int s = 0;
#pragma unroll
        for (int k = 0; k < 4; ++k) { const int v = s_warp[k]; s_warp[k] = s; s += v; }
        s_len = s;
    }
    __syncthreads();
    int pos = s_warp[wid] + excl;
#pragma unroll
    for (int j = 0; j < 8; ++j) {
        if (bytes[j]) s_list[pos++] = ((uint32_t)(tid * 8 + j) << 8) | bytes[j];
    }
    __syncthreads();
    const int len = s_len;

    // ---- sparse accumulate: 8 t x 2 f32x2 (4 n's) ----
    unsigned long long acc[T][2];
#pragma unroll
    for (int t = 0; t < T; ++t) { acc[t][0] = 0ull; acc[t][1] = 0ull; }

    const char* wbase = reinterpret_cast<const char*>(w2t) + tid * 16;

#pragma unroll 2
    for (int k = 0; k < len; ++k) {
        const uint32_t e = s_list[k];
        const uint32_t p = e & 255u;
        const uint32_t i = e >> 8;
        unsigned long long w01, w23;
        asm("ld.global.nc.v2.u64 {%0, %1}, [%2];"
            : "=l"(w01), "=l"(w23)
            : "l"(wbase + (size_t)i * (H1 * 4)));
#pragma unroll
        for (int t = 0; t < T; ++t) {
            // bit-test + predicated pair add: register-only, RN-exact
            asm("{ .reg .pred q;\n\t"
                "setp.ne.u32 q, %4, 0;\n\t"
                "@q add.rn.f32x2 %0, %0, %2;\n\t"
                "@q add.rn.f32x2 %1, %1, %3; }"
                : "+l"(acc[t][0]), "+l"(acc[t][1])
                : "l"(w01), "l"(w23), "r"(p & (1u << t)));
        }
    }

    // ---- LIF2 + output head (thread owns n0..n0+3) ----
    const int n0 = tid * 4;
    const float4 b2v = *reinterpret_cast<const float4*>(b2 + n0);
    const float4 w3v = *reinterpret_cast<const float4*>(w3 + n0);
    float m0 = 0.0f, m1 = 0.0f, m2 = 0.0f, m3 = 0.0f, aout = 0.0f;
#pragma unroll
    for (int t = 0; t < T; ++t) {
        float a0, a1, a2, a3;
        asm("mov.b64 {%0, %1}, %2;" : "=f"(a0), "=f"(a1) : "l"(acc[t][0]));
        asm("mov.b64 {%0, %1}, %2;" : "=f"(a2), "=f"(a3) : "l"(acc[t][1]));
        const float c0 = a0 + b2v.x, c1 = a1 + b2v.y;
        const float c2 = a2 + b2v.z, c3 = a3 + b2v.w;
        const float r0 = (m0 > 1.0f) ? 1.0f : 0.0f;   // reset on OLD mem
        const float r1 = (m1 > 1.0f) ? 1.0f : 0.0f;
        const float r2 = (m2 > 1.0f) ? 1.0f : 0.0f;
        const float r3 = (m3 > 1.0f) ? 1.0f : 0.0f;
        m0 = 0.95f * m0 + c0 - r0;
        m1 = 0.95f * m1 + c1 - r1;
        m2 = 0.95f * m2 + c2 - r2;
        m3 = 0.95f * m3 + c3 - r3;
        aout += ((m0 - 1.0f) > 0.0f) ? w3v.x : 0.0f;
        aout += ((m1 - 1.0f) > 0.0f) ? w3v.y : 0.0f;
        aout += ((m2 - 1.0f) > 0.0f) ? w3v.z : 0.0f;
        aout += ((m3 - 1.0f) > 0.0f) ? w3v.w : 0.0f;
    }

    // block reduce (128 threads)
#pragma unroll
    for (int d = 16; d > 0; d >>= 1)
        aout += __shfl_down_sync(0xFFFFFFFFu, aout, d);
    if (lane == 0) s_red[wid] = aout;
    __syncthreads();
    if (tid == 0) {
        out[b] = (s_red[0] + s_red[1] + s_red[2] + s_red[3]) * (1.0f / T)
               + __ldg(&b3[0]);
    }
}

// ---------------------------------------------------------------------------
extern "C" void kernel_launch(void* const* d_in, const int* in_sizes, int n_in,
                              void* d_out, int out_size)
{
    const float* data = (const float*)d_in[0];
    const float* w1   = (const float*)d_in[1];
    const float* b1   = (const float*)d_in[2];
    const float* w2   = (const float*)d_in[3];
    const float* b2   = (const float*)d_in[4];
    const float* w3   = (const float*)d_in[5];
    const float* b3   = (const float*)d_in[6];
    float* out = (float*)d_out;

    unsigned char* pack;
    float *w2t, *cur1;
    cudaGetSymbolAddress((void**)&pack, g_pack);
    cudaGetSymbolAddress((void**)&w2t,  g_w2t);
    cudaGetSymbolAddress((void**)&cur1, g_cur1);

    // 1) GEMM1 (fp32 SIMT): cur1 = data @ w1^T + b1
    {
        dim3 grid(H0 / 128, BB / 128);   // (8, 128)
        sgemm1_kernel<<<grid, 256>>>(data, w1, b1, cur1, BB, H0, DIN);
    }

    // 2) transpose w2 -> w2t [H0][H1]
    {
        dim3 grid(H0 / 32, H1 / 32);     // (32, 16)
        transpose_w2_kernel<<<grid, dim3(32, 8)>>>(w2, w2t);
    }

    // 3) LIF1 spikes -> packed bytes
    {
        const size_t n = (size_t)BB * H0;
        spike_pack_kernel<<<(unsigned)((n + 255) / 256), 256>>>(cur1, pack);
    }

    // 4) fused sparse layer-2 + LIF2 + output head
    snn_tail_kernel<<<BB, 128>>>(pack, w2t, b2, w3, b3, out);
}

// round 8
// speedup vs baseline: 2.1114x; 2.1114x over previous
#include <cuda_runtime.h>
#include <cstdint>
#include <cstddef>

// ---------------------------------------------------------------------------
// SNN forward:
//   cur1 = data @ w1^T + b1      -- fp32 SIMT GEMM (round-1 verbatim numerics)
//   pack[b,i] = 8 spike bits     -- elementwise LIF1 (beta1 = 1.0)
//   tail kernel v3 (per batch row b):
//     1) compact nonzero pattern bytes (~41% density)
//     2) DETERMINISTIC counting sort of active i's by pattern byte
//        (beta1=1 + const input => only ~37 distinct patterns)
//     3) per pattern-run: plain add.rn.f32x2 pair-sum (2 issues/entry),
//        ONE predicated merge into the 8 per-t accumulators per run
//        (R7 ncu: alu=83.9% from per-entry bit tests -- now hoisted)
//     4) LIF2 + dot(w3) + mean fused in-register -> out[b]
// ---------------------------------------------------------------------------

static constexpr int BB  = 16384;
static constexpr int DIN = 512;
static constexpr int H0  = 1024;
static constexpr int H1  = 512;
static constexpr int T   = 8;

// Scratch (device globals -- no runtime allocation allowed)
__device__ __align__(256) unsigned char g_pack[(size_t)BB * H0];  // 16 MB
__device__ __align__(256) float         g_w2t [(size_t)H0 * H1]; //  2 MB
__device__ __align__(256) float         g_cur1[(size_t)BB * H0]; // 64 MB

// ===========================================================================
// GEMM1: round-1 fp32 SIMT SGEMM (verbatim -- known-good numerics).
// ===========================================================================
__global__ void __launch_bounds__(256) sgemm1_kernel(
    const float* __restrict__ A,
    const float* __restrict__ W,
    const float* __restrict__ bias,
    float* __restrict__ C,
    int M, int N, int K)
{
    __shared__ float As[16][128];
    __shared__ float Bs[16][128];

    const int tx = threadIdx.x;
    const int tm = tx >> 4;
    const int tn = tx & 15;

    const int m0 = blockIdx.y * 128;
    const int n0 = blockIdx.x * 128;

    float acc[8][8];
#pragma unroll
    for (int i = 0; i < 8; ++i)
#pragma unroll
        for (int j = 0; j < 8; ++j) acc[i][j] = 0.0f;

    for (int kt = 0; kt < K; kt += 16) {
#pragma unroll
        for (int s = 0; s < 2; ++s) {
            const int f  = tx + s * 256;
            const int r  = f >> 2;
            const int c4 = (f & 3) * 4;
            const int gk = kt + c4;
            {
                const int gm = m0 + r;
                float4 v = *reinterpret_cast<const float4*>(&A[(size_t)gm * K + gk]);
                As[c4 + 0][r] = v.x;
                As[c4 + 1][r] = v.y;
                As[c4 + 2][r] = v.z;
                As[c4 + 3][r] = v.w;
            }
            {
                const int gn = n0 + r;
                const float4 w = *reinterpret_cast<const float4*>(&W[(size_t)gn * K + gk]);
                Bs[c4 + 0][r] = w.x;
                Bs[c4 + 1][r] = w.y;
                Bs[c4 + 2][r] = w.z;
                Bs[c4 + 3][r] = w.w;
            }
        }
        __syncthreads();

#pragma unroll
        for (int k = 0; k < 16; ++k) {
            float a[8], b[8];
            *reinterpret_cast<float4*>(&a[0]) =
                *reinterpret_cast<const float4*>(&As[k][tm * 8]);
            *reinterpret_cast<float4*>(&a[4]) =
                *reinterpret_cast<const float4*>(&As[k][tm * 8 + 4]);
            *reinterpret_cast<float4*>(&b[0]) =
                *reinterpret_cast<const float4*>(&Bs[k][tn * 8]);
            *reinterpret_cast<float4*>(&b[4]) =
                *reinterpret_cast<const float4*>(&Bs[k][tn * 8 + 4]);
#pragma unroll
            for (int i = 0; i < 8; ++i)
#pragma unroll
                for (int j = 0; j < 8; ++j)
                    acc[i][j] = fmaf(a[i], b[j], acc[i][j]);
        }
        __syncthreads();
    }

    float bj[8];
    const int gn0 = n0 + tn * 8;
#pragma unroll
    for (int j = 0; j < 8; ++j) bj[j] = __ldg(&bias[gn0 + j]);

#pragma unroll
    for (int i = 0; i < 8; ++i) {
        const int gm = m0 + tm * 8 + i;
        float4 o0, o1;
        o0.x = acc[i][0] + bj[0];
        o0.y = acc[i][1] + bj[1];
        o0.z = acc[i][2] + bj[2];
        o0.w = acc[i][3] + bj[3];
        o1.x = acc[i][4] + bj[4];
        o1.y = acc[i][5] + bj[5];
        o1.z = acc[i][6] + bj[6];
        o1.w = acc[i][7] + bj[7];
        *reinterpret_cast<float4*>(&C[(size_t)gm * N + gn0])     = o0;
        *reinterpret_cast<float4*>(&C[(size_t)gm * N + gn0 + 4]) = o1;
    }
}

// ===========================================================================
// LIF layer 1 (beta1 = 1.0): 8 spike bits packed into one byte per (b,i)
// ===========================================================================
__global__ void spike_pack_kernel(const float* __restrict__ cur1,
                                  unsigned char* __restrict__ pack)
{
    const size_t i = (size_t)blockIdx.x * blockDim.x + threadIdx.x;
    if (i >= (size_t)BB * H0) return;
    const float c = cur1[i];
    float mem = 0.0f;
    unsigned p = 0;
#pragma unroll
    for (int t = 0; t < T; ++t) {
        const float reset = (mem > 1.0f) ? 1.0f : 0.0f;   // OLD mem
        mem = mem + c - reset;                             // beta1 = 1.0
        p |= ((mem - 1.0f) > 0.0f ? 1u : 0u) << t;
    }
    pack[i] = (unsigned char)p;
}

// ===========================================================================
// Transpose w2 [H1][H0] -> w2t [H0][H1]
// ===========================================================================
__global__ void transpose_w2_kernel(const float* __restrict__ w2,
                                    float* __restrict__ w2t)
{
    __shared__ float tile[32][33];
    const int bx = blockIdx.x * 32;
    const int by = blockIdx.y * 32;
    const int tx = threadIdx.x, ty = threadIdx.y;
#pragma unroll
    for (int j = 0; j < 32; j += 8)
        tile[ty + j][tx] = w2[(size_t)(by + ty + j) * H0 + bx + tx];
    __syncthreads();
#pragma unroll
    for (int j = 0; j < 32; j += 8)
        w2t[(size_t)(bx + ty + j) * H1 + by + tx] = tile[tx][ty + j];
}

// ===========================================================================
// Fused tail v3 (128 threads, thread owns n0 = tid*4 .. +3)
// ===========================================================================
__global__ void __launch_bounds__(128) snn_tail_kernel(
    const unsigned char* __restrict__ pack,   // [BB][H0]
    const float* __restrict__ w2t,            // [H0][H1]
    const float* __restrict__ b2,
    const float* __restrict__ w3,
    const float* __restrict__ b3,
    float* __restrict__ out)
{
    __shared__ uint16_t s_idx[H0];        // i's grouped by pattern
    __shared__ int      s_cnt[256];       // per-pattern count
    __shared__ int      s_start[256];     // per-pattern exclusive start
    __shared__ int      s_wbase[4][256];  // histogram -> per-warp cursor
    __shared__ int      s_binlist[256];   // compacted nonempty patterns
    __shared__ int      s_w4a[4], s_w4b[4];
    __shared__ int      s_nbins;
    __shared__ float    s_red[4];

    const int b    = blockIdx.x;
    const int tid  = threadIdx.x;
    const int lane = tid & 31;
    const int wid  = tid >> 5;
    const unsigned FULL = 0xFFFFFFFFu;

    // ---- load pattern bytes (thread owns i = tid*8 .. tid*8+7) ----
    const uint2 wd =
        reinterpret_cast<const uint2*>(pack)[(size_t)b * (H0 / 8) + tid];
    uint32_t bytes[8];
#pragma unroll
    for (int j = 0; j < 4; ++j) {
        bytes[j]     = (wd.x >> (8 * j)) & 255u;
        bytes[4 + j] = (wd.y >> (8 * j)) & 255u;
    }

    // ---- zero per-warp histogram ----
#pragma unroll
    for (int k = 0; k < 8; ++k) s_wbase[(tid * 8 + k) >> 8][(tid * 8 + k) & 255] = 0;
    __syncthreads();

    // ---- per-warp histogram (zeros excluded) ----
#pragma unroll
    for (int j = 0; j < 8; ++j)
        if (bytes[j]) atomicAdd(&s_wbase[wid][bytes[j]], 1);
    __syncthreads();

    // ---- totals (2 patterns per thread) ----
    const int p0 = tid * 2, p1 = tid * 2 + 1;
    const int v0 = s_wbase[0][p0] + s_wbase[1][p0] + s_wbase[2][p0] + s_wbase[3][p0];
    const int v1 = s_wbase[0][p1] + s_wbase[1][p1] + s_wbase[2][p1] + s_wbase[3][p1];

    // ---- exclusive scan over 256 counts (pair per thread) ----
    {
        int inc = v0 + v1;
#pragma unroll
        for (int d = 1; d < 32; d <<= 1) {
            const int t = __shfl_up_sync(FULL, inc, d);
            if (lane >= d) inc += t;
        }
        if (lane == 31) s_w4a[wid] = inc;
        __syncthreads();
        int woff = 0;
#pragma unroll
        for (int w = 0; w < 4; ++w) woff += (w < wid) ? s_w4a[w] : 0;
        const int e0 = woff + inc - (v0 + v1);
        s_start[p0] = e0;
        s_start[p1] = e0 + v0;
        s_cnt[p0] = v0;
        s_cnt[p1] = v1;
    }

    // ---- compact nonempty pattern list (exclude pattern 0) ----
    {
        const int f0 = (p0 != 0 && v0 > 0) ? 1 : 0;
        const int f1 = (v1 > 0) ? 1 : 0;
        int inc = f0 + f1;
#pragma unroll
        for (int d = 1; d < 32; d <<= 1) {
            const int t = __shfl_up_sync(FULL, inc, d);
            if (lane >= d) inc += t;
        }
        if (lane == 31) s_w4b[wid] = inc;
        __syncthreads();
        int woff = 0;
#pragma unroll
        for (int w = 0; w < 4; ++w) woff += (w < wid) ? s_w4b[w] : 0;
        const int c0 = woff + inc - (f0 + f1);
        if (f0) s_binlist[c0] = p0;
        if (f1) s_binlist[c0 + f0] = p1;
        if (tid == 127) s_nbins = c0 + f0 + f1;
    }
    __syncthreads();

    // ---- convert histogram to per-warp cursors ----
    {
#pragma unroll
        for (int pp = 0; pp < 2; ++pp) {
            const int p = tid * 2 + pp;
            int run = s_start[p];
#pragma unroll
            for (int w = 0; w < 4; ++w) {
                const int t = s_wbase[w][p];
                s_wbase[w][p] = run;
                run += t;
            }
        }
    }
    __syncthreads();

    // ---- deterministic scatter: slot-sequential, per-warp cursors ----
#pragma unroll
    for (int j = 0; j < 8; ++j) {
        const uint32_t bj = bytes[j];
        const uint32_t grp = __match_any_sync(FULL, bj);
        const int leader = __ffs(grp) - 1;
        int base = 0;
        if (bj && lane == leader)
            base = atomicAdd(&s_wbase[wid][bj], __popc(grp));
        base = __shfl_sync(FULL, base, leader);
        if (bj) {
            const int pos = base + __popc(grp & ((1u << lane) - 1u));
            s_idx[pos] = (uint16_t)(tid * 8 + j);
        }
    }
    __syncthreads();

    // ---- run-hoisted sparse accumulation ----
    unsigned long long acc[T][2];
#pragma unroll
    for (int t = 0; t < T; ++t) { acc[t][0] = 0ull; acc[t][1] = 0ull; }

    const char* wbase = reinterpret_cast<const char*>(w2t) + tid * 16;
    const int nbins = s_nbins;

    for (int bi = 0; bi < nbins; ++bi) {
        const int p  = s_binlist[bi];
        const int st = s_start[p];
        const int en = st + s_cnt[p];

        unsigned long long rs0 = 0ull, rs1 = 0ull;
        for (int k = st; k < en; ++k) {
            const uint32_t i = s_idx[k];
            unsigned long long w01, w23;
            asm("ld.global.nc.v2.u64 {%0, %1}, [%2];"
                : "=l"(w01), "=l"(w23)
                : "l"(wbase + (size_t)i * (H1 * 4)));
            asm("add.rn.f32x2 %0, %0, %1;" : "+l"(rs0) : "l"(w01));
            asm("add.rn.f32x2 %0, %0, %1;" : "+l"(rs1) : "l"(w23));
        }

        // merge run-sum into the per-t accumulators (bits of p)
#pragma unroll
        for (int t = 0; t < T; ++t) {
            asm("{ .reg .pred q;\n\t"
                "setp.ne.u32 q, %4, 0;\n\t"
                "@q add.rn.f32x2 %0, %0, %2;\n\t"
                "@q add.rn.f32x2 %1, %1, %3; }"
                : "+l"(acc[t][0]), "+l"(acc[t][1])
                : "l"(rs0), "l"(rs1), "r"((unsigned)p & (1u << t)));
        }
    }

    // ---- LIF2 + output head (thread owns n0..n0+3) ----
    const int n0 = tid * 4;
    const float4 b2v = *reinterpret_cast<const float4*>(b2 + n0);
    const float4 w3v = *reinterpret_cast<const float4*>(w3 + n0);
    float m0 = 0.0f, m1 = 0.0f, m2 = 0.0f, m3 = 0.0f, aout = 0.0f;
#pragma unroll
    for (int t = 0; t < T; ++t) {
        float a0, a1, a2, a3;
        asm("mov.b64 {%0, %1}, %2;" : "=f"(a0), "=f"(a1) : "l"(acc[t][0]));
        asm("mov.b64 {%0, %1}, %2;" : "=f"(a2), "=f"(a3) : "l"(acc[t][1]));
        const float c0 = a0 + b2v.x, c1 = a1 + b2v.y;
        const float c2 = a2 + b2v.z, c3 = a3 + b2v.w;
        const float r0 = (m0 > 1.0f) ? 1.0f : 0.0f;   // reset on OLD mem
        const float r1 = (m1 > 1.0f) ? 1.0f : 0.0f;
        const float r2 = (m2 > 1.0f) ? 1.0f : 0.0f;
        const float r3 = (m3 > 1.0f) ? 1.0f : 0.0f;
        m0 = 0.95f * m0 + c0 - r0;
        m1 = 0.95f * m1 + c1 - r1;
        m2 = 0.95f * m2 + c2 - r2;
        m3 = 0.95f * m3 + c3 - r3;
        aout += ((m0 - 1.0f) > 0.0f) ? w3v.x : 0.0f;
        aout += ((m1 - 1.0f) > 0.0f) ? w3v.y : 0.0f;
        aout += ((m2 - 1.0f) > 0.0f) ? w3v.z : 0.0f;
        aout += ((m3 - 1.0f) > 0.0f) ? w3v.w : 0.0f;
    }

    // block reduce (128 threads)
#pragma unroll
    for (int d = 16; d > 0; d >>= 1)
        aout += __shfl_down_sync(FULL, aout, d);
    if (lane == 0) s_red[wid] = aout;
    __syncthreads();
    if (tid == 0) {
        out[b] = (s_red[0] + s_red[1] + s_red[2] + s_red[3]) * (1.0f / T)
               + __ldg(&b3[0]);
    }
}

// ---------------------------------------------------------------------------
extern "C" void kernel_launch(void* const* d_in, const int* in_sizes, int n_in,
                              void* d_out, int out_size)
{
    const float* data = (const float*)d_in[0];
    const float* w1   = (const float*)d_in[1];
    const float* b1   = (const float*)d_in[2];
    const float* w2   = (const float*)d_in[3];
    const float* b2   = (const float*)d_in[4];
    const float* w3   = (const float*)d_in[5];
    const float* b3   = (const float*)d_in[6];
    float* out = (float*)d_out;

    unsigned char* pack;
    float *w2t, *cur1;
    cudaGetSymbolAddress((void**)&pack, g_pack);
    cudaGetSymbolAddress((void**)&w2t,  g_w2t);
    cudaGetSymbolAddress((void**)&cur1, g_cur1);

    // 1) GEMM1 (fp32 SIMT): cur1 = data @ w1^T + b1
    {
        dim3 grid(H0 / 128, BB / 128);   // (8, 128)
        sgemm1_kernel<<<grid, 256>>>(data, w1, b1, cur1, BB, H0, DIN);
    }

    // 2) transpose w2 -> w2t [H0][H1]
    {
        dim3 grid(H0 / 32, H1 / 32);     // (32, 16)
        transpose_w2_kernel<<<grid, dim3(32, 8)>>>(w2, w2t);
    }

    // 3) LIF1 spikes -> packed bytes
    {
        const size_t n = (size_t)BB * H0;
        spike_pack_kernel<<<(unsigned)((n + 255) / 256), 256>>>(cur1, pack);
    }

    // 4) fused sparse layer-2 + LIF2 + output head
    snn_tail_kernel<<<BB, 128>>>(pack, w2t, b2, w3, b3, out);
}

// round 9
// speedup vs baseline: 2.2739x; 1.0769x over previous
#include <cuda_runtime.h>
#include <cstdint>
#include <cstddef>

// ---------------------------------------------------------------------------
// SNN forward:
//   GEMM1+pack: cur1 = data @ w1^T + b1 computed in-register (double-buffered
//     SIMT fp32, R1-identical arithmetic) -> LIF1 (beta1=1) pattern byte per
//     (b,i) written directly (cur1 never materialized)
//   tail kernel (per batch row b): deterministic counting sort of active i's
//     by pattern byte (~37 distinct patterns), per-run plain f32x2 pair-sums,
//     one predicated merge per run; LIF2 + dot(w3) + mean in-register.
//   R8 ncu: tail L2-bound (75.7%) -> w2t loads get L1::evict_last.
// ---------------------------------------------------------------------------

static constexpr int BB  = 16384;
static constexpr int DIN = 512;
static constexpr int H0  = 1024;
static constexpr int H1  = 512;
static constexpr int T   = 8;

// Scratch (device globals -- no runtime allocation allowed)
__device__ __align__(256) unsigned char g_pack[(size_t)BB * H0];  // 16 MB
__device__ __align__(256) float         g_w2t [(size_t)H0 * H1]; //  2 MB

// ===========================================================================
// GEMM1 + fused LIF1 pack.
// C-tile arithmetic identical to the R1 sgemm1_kernel (same 128x128x16
// tiling, same smem layout, same FMA order); only data staging is
// double-buffered, and the epilogue emits pattern bytes instead of cur1.
// ===========================================================================
__global__ void __launch_bounds__(256) sgemm1_pack_kernel(
    const float* __restrict__ A,
    const float* __restrict__ W,
    const float* __restrict__ bias,
    unsigned char* __restrict__ pack,
    int M, int N, int K)
{
    __shared__ float As[2][16][128];
    __shared__ float Bs[2][16][128];

    const int tx = threadIdx.x;
    const int tm = tx >> 4;
    const int tn = tx & 15;

    const int m0 = blockIdx.y * 128;
    const int n0 = blockIdx.x * 128;

    // per-thread gmem staging coords (same element mapping as R1 loads)
    const int f0 = tx;          // float4 id, part 0
    const int f1 = tx + 256;    // float4 id, part 1
    const int r0 = f0 >> 2, c40 = (f0 & 3) * 4;
    const int r1 = f1 >> 2, c41 = (f1 & 3) * 4;

    float acc[8][8];
#pragma unroll
    for (int i = 0; i < 8; ++i)
#pragma unroll
        for (int j = 0; j < 8; ++j) acc[i][j] = 0.0f;

    float4 ra0, ra1, rb0, rb1;

    auto load_regs = [&](int kt) {
        ra0 = *reinterpret_cast<const float4*>(&A[(size_t)(m0 + r0) * K + kt + c40]);
        ra1 = *reinterpret_cast<const float4*>(&A[(size_t)(m0 + r1) * K + kt + c41]);
        rb0 = *reinterpret_cast<const float4*>(&W[(size_t)(n0 + r0) * K + kt + c40]);
        rb1 = *reinterpret_cast<const float4*>(&W[(size_t)(n0 + r1) * K + kt + c41]);
    };
    auto store_smem = [&](int buf) {
        As[buf][c40 + 0][r0] = ra0.x;
        As[buf][c40 + 1][r0] = ra0.y;
        As[buf][c40 + 2][r0] = ra0.z;
        As[buf][c40 + 3][r0] = ra0.w;
        As[buf][c41 + 0][r1] = ra1.x;
        As[buf][c41 + 1][r1] = ra1.y;
        As[buf][c41 + 2][r1] = ra1.z;
        As[buf][c41 + 3][r1] = ra1.w;
        Bs[buf][c40 + 0][r0] = rb0.x;
        Bs[buf][c40 + 1][r0] = rb0.y;
        Bs[buf][c40 + 2][r0] = rb0.z;
        Bs[buf][c40 + 3][r0] = rb0.w;
        Bs[buf][c41 + 0][r1] = rb1.x;
        Bs[buf][c41 + 1][r1] = rb1.y;
        Bs[buf][c41 + 2][r1] = rb1.z;
        Bs[buf][c41 + 3][r1] = rb1.w;
    };

    // prologue
    load_regs(0);
    store_smem(0);
    __syncthreads();

    const int nt = K / 16;
    for (int it = 0; it < nt; ++it) {
        const int buf = it & 1;
        const bool more = (it + 1 < nt);
        if (more) load_regs((it + 1) * 16);   // overlap with compute below

#pragma unroll
        for (int k = 0; k < 16; ++k) {
            float a[8], b[8];
            *reinterpret_cast<float4*>(&a[0]) =
                *reinterpret_cast<const float4*>(&As[buf][k][tm * 8]);
            *reinterpret_cast<float4*>(&a[4]) =
                *reinterpret_cast<const float4*>(&As[buf][k][tm * 8 + 4]);
            *reinterpret_cast<float4*>(&b[0]) =
                *reinterpret_cast<const float4*>(&Bs[buf][k][tn * 8]);
            *reinterpret_cast<float4*>(&b[4]) =
                *reinterpret_cast<const float4*>(&Bs[buf][k][tn * 8 + 4]);
#pragma unroll
            for (int i = 0; i < 8; ++i)
#pragma unroll
                for (int j = 0; j < 8; ++j)
                    acc[i][j] = fmaf(a[i], b[j], acc[i][j]);
        }

        if (more) {
            store_smem(buf ^ 1);   // buf^1 fully consumed before prev barrier
            __syncthreads();
        }
    }

    // ---- epilogue: bias add + LIF1 (beta1 = 1.0) -> pattern bytes ----
    float bj[8];
    const int gn0 = n0 + tn * 8;
#pragma unroll
    for (int j = 0; j < 8; ++j) bj[j] = __ldg(&bias[gn0 + j]);

#pragma unroll
    for (int i = 0; i < 8; ++i) {
        const int gm = m0 + tm * 8 + i;        // batch index
        unsigned long long u = 0ull;
#pragma unroll
        for (int j = 0; j < 8; ++j) {
            const float c = acc[i][j] + bj[j];  // == cur1 value (bit-identical)
            float mem = 0.0f;
            unsigned p = 0;
#pragma unroll
            for (int t = 0; t < T; ++t) {
                const float reset = (mem > 1.0f) ? 1.0f : 0.0f;   // OLD mem
                mem = mem + c - reset;                             // beta1 = 1.0
                p |= ((mem - 1.0f) > 0.0f ? 1u : 0u) << t;
            }
            u |= (unsigned long long)p << (8 * j);
        }
        *reinterpret_cast<unsigned long long*>(&pack[(size_t)gm * N + gn0]) = u;
    }
}

// ===========================================================================
// Transpose w2 [H1][H0] -> w2t [H0][H1]
// ===========================================================================
__global__ void transpose_w2_kernel(const float* __restrict__ w2,
                                    float* __restrict__ w2t)
{
    __shared__ float tile[32][33];
    const int bx = blockIdx.x * 32;
    const int by = blockIdx.y * 32;
    const int tx = threadIdx.x, ty = threadIdx.y;
#pragma unroll
    for (int j = 0; j < 32; j += 8)
        tile[ty + j][tx] = w2[(size_t)(by + ty + j) * H0 + bx + tx];
    __syncthreads();
#pragma unroll
    for (int j = 0; j < 32; j += 8)
        w2t[(size_t)(bx + ty + j) * H1 + by + tx] = tile[tx][ty + j];
}

// ===========================================================================
// Fused tail (R8, unchanged arithmetic; w2t loads get L1::evict_last)
// ===========================================================================
__global__ void __launch_bounds__(128) snn_tail_kernel(
    const unsigned char* __restrict__ pack,   // [BB][H0]
    const float* __restrict__ w2t,            // [H0][H1]
    const float* __restrict__ b2,
    const float* __restrict__ w3,
    const float* __restrict__ b3,
    float* __restrict__ out)
{
    __shared__ uint16_t s_idx[H0];
    __shared__ int      s_cnt[256];
    __shared__ int      s_start[256];
    __shared__ int      s_wbase[4][256];
    __shared__ int      s_binlist[256];
    __shared__ int      s_w4a[4], s_w4b[4];
    __shared__ int      s_nbins;
    __shared__ float    s_red[4];

    const int b    = blockIdx.x;
    const int tid  = threadIdx.x;
    const int lane = tid & 31;
    const int wid  = tid >> 5;
    const unsigned FULL = 0xFFFFFFFFu;

    const uint2 wd =
        reinterpret_cast<const uint2*>(pack)[(size_t)b * (H0 / 8) + tid];
    uint32_t bytes[8];
#pragma unroll
    for (int j = 0; j < 4; ++j) {
        bytes[j]     = (wd.x >> (8 * j)) & 255u;
        bytes[4 + j] = (wd.y >> (8 * j)) & 255u;
    }

#pragma unroll
    for (int k = 0; k < 8; ++k) s_wbase[(tid * 8 + k) >> 8][(tid * 8 + k) & 255] = 0;
    __syncthreads();

#pragma unroll
    for (int j = 0; j < 8; ++j)
        if (bytes[j]) atomicAdd(&s_wbase[wid][bytes[j]], 1);
    __syncthreads();

    const int p0 = tid * 2, p1 = tid * 2 + 1;
    const int v0 = s_wbase[0][p0] + s_wbase[1][p0] + s_wbase[2][p0] + s_wbase[3][p0];
    const int v1 = s_wbase[0][p1] + s_wbase[1][p1] + s_wbase[2][p1] + s_wbase[3][p1];

    {
        int inc = v0 + v1;
#pragma unroll
        for (int d = 1; d < 32; d <<= 1) {
            const int t = __shfl_up_sync(FULL, inc, d);
            if (lane >= d) inc += t;
        }
        if (lane == 31) s_w4a[wid] = inc;
        __syncthreads();
        int woff = 0;
#pragma unroll
        for (int w = 0; w < 4; ++w) woff += (w < wid) ? s_w4a[w] : 0;
        const int e0 = woff + inc - (v0 + v1);
        s_start[p0] = e0;
        s_start[p1] = e0 + v0;
        s_cnt[p0] = v0;
        s_cnt[p1] = v1;
    }

    {
        const int f0 = (p0 != 0 && v0 > 0) ? 1 : 0;
        const int f1 = (v1 > 0) ? 1 : 0;
        int inc = f0 + f1;
#pragma unroll
        for (int d = 1; d < 32; d <<= 1) {
            const int t = __shfl_up_sync(FULL, inc, d);
            if (lane >= d) inc += t;
        }
        if (lane == 31) s_w4b[wid] = inc;
        __syncthreads();
        int woff = 0;
#pragma unroll
        for (int w = 0; w < 4; ++w) woff += (w < wid) ? s_w4b[w] : 0;
        const int c0 = woff + inc - (f0 + f1);
        if (f0) s_binlist[c0] = p0;
        if (f1) s_binlist[c0 + f0] = p1;
        if (tid == 127) s_nbins = c0 + f0 + f1;
    }
    __syncthreads();

    {
#pragma unroll
        for (int pp = 0; pp < 2; ++pp) {
            const int p = tid * 2 + pp;
            int run = s_start[p];
#pragma unroll
            for (int w = 0; w < 4; ++w) {
                const int t = s_wbase[w][p];
                s_wbase[w][p] = run;
                run += t;
            }
        }
    }
    __syncthreads();

#pragma unroll
    for (int j = 0; j < 8; ++j) {
        const uint32_t bj = bytes[j];
        const uint32_t grp = __match_any_sync(FULL, bj);
        const int leader = __ffs(grp) - 1;
        int base = 0;
        if (bj && lane == leader)
            base = atomicAdd(&s_wbase[wid][bj], __popc(grp));
        base = __shfl_sync(FULL, base, leader);
        if (bj) {
            const int pos = base + __popc(grp & ((1u << lane) - 1u));
            s_idx[pos] = (uint16_t)(tid * 8 + j);
        }
    }
    __syncthreads();

    unsigned long long acc[T][2];
#pragma unroll
    for (int t = 0; t < T; ++t) { acc[t][0] = 0ull; acc[t][1] = 0ull; }

    const char* wbase = reinterpret_cast<const char*>(w2t) + tid * 16;
    const int nbins = s_nbins;

    for (int bi = 0; bi < nbins; ++bi) {
        const int p  = s_binlist[bi];
        const int st = s_start[p];
        const int en = st + s_cnt[p];

        unsigned long long rs0 = 0ull, rs1 = 0ull;
        for (int k = st; k < en; ++k) {
            const uint32_t i = s_idx[k];
            unsigned long long w01, w23;
            asm("ld.global.nc.L1::evict_last.v2.u64 {%0, %1}, [%2];"
                : "=l"(w01), "=l"(w23)
                : "l"(wbase + (size_t)i * (H1 * 4)));
            asm("add.rn.f32x2 %0, %0, %1;" : "+l"(rs0) : "l"(w01));
            asm("add.rn.f32x2 %0, %0, %1;" : "+l"(rs1) : "l"(w23));
        }

#pragma unroll
        for (int t = 0; t < T; ++t) {
            asm("{ .reg .pred q;\n\t"
                "setp.ne.u32 q, %4, 0;\n\t"
                "@q add.rn.f32x2 %0, %0, %2;\n\t"
                "@q add.rn.f32x2 %1, %1, %3; }"
                : "+l"(acc[t][0]), "+l"(acc[t][1])
                : "l"(rs0), "l"(rs1), "r"((unsigned)p & (1u << t)));
        }
    }

    const int n0 = tid * 4;
    const float4 b2v = *reinterpret_cast<const float4*>(b2 + n0);
    const float4 w3v = *reinterpret_cast<const float4*>(w3 + n0);
    float m0 = 0.0f, m1 = 0.0f, m2 = 0.0f, m3 = 0.0f, aout = 0.0f;
#pragma unroll
    for (int t = 0; t < T; ++t) {
        float a0, a1, a2, a3;
        asm("mov.b64 {%0, %1}, %2;" : "=f"(a0), "=f"(a1) : "l"(acc[t][0]));
        asm("mov.b64 {%0, %1}, %2;" : "=f"(a2), "=f"(a3) : "l"(acc[t][1]));
        const float c0 = a0 + b2v.x, c1 = a1 + b2v.y;
        const float c2 = a2 + b2v.z, c3 = a3 + b2v.w;
        const float r0 = (m0 > 1.0f) ? 1.0f : 0.0f;   // reset on OLD mem
        const float r1 = (m1 > 1.0f) ? 1.0f : 0.0f;
        const float r2 = (m2 > 1.0f) ? 1.0f : 0.0f;
        const float r3 = (m3 > 1.0f) ? 1.0f : 0.0f;
        m0 = 0.95f * m0 + c0 - r0;
        m1 = 0.95f * m1 + c1 - r1;
        m2 = 0.95f * m2 + c2 - r2;
        m3 = 0.95f * m3 + c3 - r3;
        aout += ((m0 - 1.0f) > 0.0f) ? w3v.x : 0.0f;
        aout += ((m1 - 1.0f) > 0.0f) ? w3v.y : 0.0f;
        aout += ((m2 - 1.0f) > 0.0f) ? w3v.z : 0.0f;
        aout += ((m3 - 1.0f) > 0.0f) ? w3v.w : 0.0f;
    }

#pragma unroll
    for (int d = 16; d > 0; d >>= 1)
        aout += __shfl_down_sync(FULL, aout, d);
    if (lane == 0) s_red[wid] = aout;
    __syncthreads();
    if (tid == 0) {
        out[b] = (s_red[0] + s_red[1] + s_red[2] + s_red[3]) * (1.0f / T)
               + __ldg(&b3[0]);
    }
}

// ---------------------------------------------------------------------------
extern "C" void kernel_launch(void* const* d_in, const int* in_sizes, int n_in,
                              void* d_out, int out_size)
{
    const float* data = (const float*)d_in[0];
    const float* w1   = (const float*)d_in[1];
    const float* b1   = (const float*)d_in[2];
    const float* w2   = (const float*)d_in[3];
    const float* b2   = (const float*)d_in[4];
    const float* w3   = (const float*)d_in[5];
    const float* b3   = (const float*)d_in[6];
    float* out = (float*)d_out;

    unsigned char* pack;
    float* w2t;
    cudaGetSymbolAddress((void**)&pack, g_pack);
    cudaGetSymbolAddress((void**)&w2t,  g_w2t);

    // 1) transpose w2 -> w2t [H0][H1]
    {
        dim3 grid(H0 / 32, H1 / 32);     // (32, 16)
        transpose_w2_kernel<<<grid, dim3(32, 8)>>>(w2, w2t);
    }

    // 2) GEMM1 + fused LIF1 pack (cur1 never materialized)
    {
        dim3 grid(H0 / 128, BB / 128);   // (8, 128)
        sgemm1_pack_kernel<<<grid, 256>>>(data, w1, b1, pack, BB, H0, DIN);
    }

    // 3) fused sparse layer-2 + LIF2 + output head
    snn_tail_kernel<<<BB, 128>>>(pack, w2t, b2, w3, b3, out);
}

// round 10
// speedup vs baseline: 2.3019x; 1.0123x over previous
#include <cuda_runtime.h>
#include <cstdint>
#include <cstddef>

// ---------------------------------------------------------------------------
// SNN forward:
//   GEMM1+pack: cur1 = data @ w1^T + b1 via packed fp32 FFMA2 (fma.rn.f32x2,
//     2x the scalar-FFMA pipe rate; per-element arithmetic bit-identical to
//     the R1 scalar loop) -> LIF1 (beta1=1) pattern bytes, cur1 never stored.
//   tail (R8/R9, unchanged): deterministic counting sort by pattern byte,
//     per-run f32x2 pair-sums + one predicated merge per run; LIF2 + w3-dot
//     + mean in-register -> out[b].
// ---------------------------------------------------------------------------

static constexpr int BB  = 16384;
static constexpr int DIN = 512;
static constexpr int H0  = 1024;
static constexpr int H1  = 512;
static constexpr int T   = 8;

// Scratch (device globals -- no runtime allocation allowed)
__device__ __align__(256) unsigned char g_pack[(size_t)BB * H0];  // 16 MB
__device__ __align__(256) float         g_w2t [(size_t)H0 * H1]; //  2 MB

// ===========================================================================
// GEMM1 + fused LIF1 pack, FFMA2 inner loop.
// Same 128x128x16 tiling / smem layout / double buffering as R9; the 8x8
// micro-tile now accumulates in 8x4 f32x2 pairs. Lane-wise each FMA has the
// same operands in the same order, RN rounding -> cur1 bit-identical.
// ===========================================================================
__global__ void __launch_bounds__(256) sgemm1_pack_kernel(
    const float* __restrict__ A,
    const float* __restrict__ W,
    const float* __restrict__ bias,
    unsigned char* __restrict__ pack,
    int M, int N, int K)
{
    __shared__ float As[2][16][128];
    __shared__ float Bs[2][16][128];

    const int tx = threadIdx.x;
    const int tm = tx >> 4;
    const int tn = tx & 15;

    const int m0 = blockIdx.y * 128;
    const int n0 = blockIdx.x * 128;

    const int f0 = tx;          // float4 id, part 0
    const int f1 = tx + 256;    // float4 id, part 1
    const int r0 = f0 >> 2, c40 = (f0 & 3) * 4;
    const int r1 = f1 >> 2, c41 = (f1 & 3) * 4;

    // accumulators: 8 rows x 4 n-pairs (f32x2)
    unsigned long long acc2[8][4];
#pragma unroll
    for (int i = 0; i < 8; ++i)
#pragma unroll
        for (int j = 0; j < 4; ++j) acc2[i][j] = 0ull;

    float4 ra0, ra1, rb0, rb1;

    auto load_regs = [&](int kt) {
        ra0 = *reinterpret_cast<const float4*>(&A[(size_t)(m0 + r0) * K + kt + c40]);
        ra1 = *reinterpret_cast<const float4*>(&A[(size_t)(m0 + r1) * K + kt + c41]);
        rb0 = *reinterpret_cast<const float4*>(&W[(size_t)(n0 + r0) * K + kt + c40]);
        rb1 = *reinterpret_cast<const float4*>(&W[(size_t)(n0 + r1) * K + kt + c41]);
    };
    auto store_smem = [&](int buf) {
        As[buf][c40 + 0][r0] = ra0.x;
        As[buf][c40 + 1][r0] = ra0.y;
        As[buf][c40 + 2][r0] = ra0.z;
        As[buf][c40 + 3][r0] = ra0.w;
        As[buf][c41 + 0][r1] = ra1.x;
        As[buf][c41 + 1][r1] = ra1.y;
        As[buf][c41 + 2][r1] = ra1.z;
        As[buf][c41 + 3][r1] = ra1.w;
        Bs[buf][c40 + 0][r0] = rb0.x;
        Bs[buf][c40 + 1][r0] = rb0.y;
        Bs[buf][c40 + 2][r0] = rb0.z;
        Bs[buf][c40 + 3][r0] = rb0.w;
        Bs[buf][c41 + 0][r1] = rb1.x;
        Bs[buf][c41 + 1][r1] = rb1.y;
        Bs[buf][c41 + 2][r1] = rb1.z;
        Bs[buf][c41 + 3][r1] = rb1.w;
    };

    // prologue
    load_regs(0);
    store_smem(0);
    __syncthreads();

    const int nt = K / 16;
    for (int it = 0; it < nt; ++it) {
        const int buf = it & 1;
        const bool more = (it + 1 < nt);
        if (more) load_regs((it + 1) * 16);   // overlap with compute below

#pragma unroll
        for (int k = 0; k < 16; ++k) {
            float a[8];
            unsigned long long b2[4];
            *reinterpret_cast<float4*>(&a[0]) =
                *reinterpret_cast<const float4*>(&As[buf][k][tm * 8]);
            *reinterpret_cast<float4*>(&a[4]) =
                *reinterpret_cast<const float4*>(&As[buf][k][tm * 8 + 4]);
            *reinterpret_cast<float4*>(&b2[0]) =
                *reinterpret_cast<const float4*>(&Bs[buf][k][tn * 8]);
            *reinterpret_cast<float4*>(&b2[2]) =
                *reinterpret_cast<const float4*>(&Bs[buf][k][tn * 8 + 4]);
#pragma unroll
            for (int i = 0; i < 8; ++i) {
                unsigned long long a2;
                asm("mov.b64 %0, {%1, %1};" : "=l"(a2) : "f"(a[i]));
#pragma unroll
                for (int j = 0; j < 4; ++j)
                    asm("fma.rn.f32x2 %0, %1, %2, %0;"
                        : "+l"(acc2[i][j]) : "l"(a2), "l"(b2[j]));
            }
        }

        if (more) {
            store_smem(buf ^ 1);   // buf^1 fully consumed before prev barrier
            __syncthreads();
        }
    }

    // ---- epilogue: bias add + LIF1 (beta1 = 1.0) -> pattern bytes ----
    float bj[8];
    const int gn0 = n0 + tn * 8;
#pragma unroll
    for (int j = 0; j < 8; ++j) bj[j] = __ldg(&bias[gn0 + j]);

#pragma unroll
    for (int i = 0; i < 8; ++i) {
        const int gm = m0 + tm * 8 + i;        // batch index
        float accf[8];
#pragma unroll
        for (int j = 0; j < 4; ++j)
            asm("mov.b64 {%0, %1}, %2;"
                : "=f"(accf[2 * j]), "=f"(accf[2 * j + 1]) : "l"(acc2[i][j]));

        unsigned long long u = 0ull;
#pragma unroll
        for (int j = 0; j < 8; ++j) {
            const float c = accf[j] + bj[j];    // == cur1 value (bit-identical)
            float mem = 0.0f;
            unsigned p = 0;
#pragma unroll
            for (int t = 0; t < T; ++t) {
                const float reset = (mem > 1.0f) ? 1.0f : 0.0f;   // OLD mem
                mem = mem + c - reset;                             // beta1 = 1.0
                p |= ((mem - 1.0f) > 0.0f ? 1u : 0u) << t;
            }
            u |= (unsigned long long)p << (8 * j);
        }
        *reinterpret_cast<unsigned long long*>(&pack[(size_t)gm * N + gn0]) = u;
    }
}

// ===========================================================================
// Transpose w2 [H1][H0] -> w2t [H0][H1]
// ===========================================================================
__global__ void transpose_w2_kernel(const float* __restrict__ w2,
                                    float* __restrict__ w2t)
{
    __shared__ float tile[32][33];
    const int bx = blockIdx.x * 32;
    const int by = blockIdx.y * 32;
    const int tx = threadIdx.x, ty = threadIdx.y;
#pragma unroll
    for (int j = 0; j < 32; j += 8)
        tile[ty + j][tx] = w2[(size_t)(by + ty + j) * H0 + bx + tx];
    __syncthreads();
#pragma unroll
    for (int j = 0; j < 32; j += 8)
        w2t[(size_t)(bx + ty + j) * H1 + by + tx] = tile[tx][ty + j];
}

// ===========================================================================
// Fused tail (R8/R9, unchanged)
// ===========================================================================
__global__ void __launch_bounds__(128) snn_tail_kernel(
    const unsigned char* __restrict__ pack,   // [BB][H0]
    const float* __restrict__ w2t,            // [H0][H1]
    const float* __restrict__ b2,
    const float* __restrict__ w3,
    const float* __restrict__ b3,
    float* __restrict__ out)
{
    __shared__ uint16_t s_idx[H0];
    __shared__ int      s_cnt[256];
    __shared__ int      s_start[256];
    __shared__ int      s_wbase[4][256];
    __shared__ int      s_binlist[256];
    __shared__ int      s_w4a[4], s_w4b[4];
    __shared__ int      s_nbins;
    __shared__ float    s_red[4];

    const int b    = blockIdx.x;
    const int tid  = threadIdx.x;
    const int lane = tid & 31;
    const int wid  = tid >> 5;
    const unsigned FULL = 0xFFFFFFFFu;

    const uint2 wd =
        reinterpret_cast<const uint2*>(pack)[(size_t)b * (H0 / 8) + tid];
    uint32_t bytes[8];
#pragma unroll
    for (int j = 0; j < 4; ++j) {
        bytes[j]     = (wd.x >> (8 * j)) & 255u;
        bytes[4 + j] = (wd.y >> (8 * j)) & 255u;
    }

#pragma unroll
    for (int k = 0; k < 8; ++k) s_wbase[(tid * 8 + k) >> 8][(tid * 8 + k) & 255] = 0;
    __syncthreads();

#pragma unroll
    for (int j = 0; j < 8; ++j)
        if (bytes[j]) atomicAdd(&s_wbase[wid][bytes[j]], 1);
    __syncthreads();

    const int p0 = tid * 2, p1 = tid * 2 + 1;
    const int v0 = s_wbase[0][p0] + s_wbase[1][p0] + s_wbase[2][p0] + s_wbase[3][p0];
    const int v1 = s_wbase[0][p1] + s_wbase[1][p1] + s_wbase[2][p1] + s_wbase[3][p1];

    {
        int inc = v0 + v1;
#pragma unroll
        for (int d = 1; d < 32; d <<= 1) {
            const int t = __shfl_up_sync(FULL, inc, d);
            if (lane >= d) inc += t;
        }
        if (lane == 31) s_w4a[wid] = inc;
        __syncthreads();
        int woff = 0;
#pragma unroll
        for (int w = 0; w < 4; ++w) woff += (w < wid) ? s_w4a[w] : 0;
        const int e0 = woff + inc - (v0 + v1);
        s_start[p0] = e0;
        s_start[p1] = e0 + v0;
        s_cnt[p0] = v0;
        s_cnt[p1] = v1;
    }

    {
        const int f0 = (p0 != 0 && v0 > 0) ? 1 : 0;
        const int f1 = (v1 > 0) ? 1 : 0;
        int inc = f0 + f1;
#pragma unroll
        for (int d = 1; d < 32; d <<= 1) {
            const int t = __shfl_up_sync(FULL, inc, d);
            if (lane >= d) inc += t;
        }
        if (lane == 31) s_w4b[wid] = inc;
        __syncthreads();
        int woff = 0;
#pragma unroll
        for (int w = 0; w < 4; ++w) woff += (w < wid) ? s_w4b[w] : 0;
        const int c0 = woff + inc - (f0 + f1);
        if (f0) s_binlist[c0] = p0;
        if (f1) s_binlist[c0 + f0] = p1;
        if (tid == 127) s_nbins = c0 + f0 + f1;
    }
    __syncthreads();

    {
#pragma unroll
        for (int pp = 0; pp < 2; ++pp) {
            const int p = tid * 2 + pp;
            int run = s_start[p];
#pragma unroll
            for (int w = 0; w < 4; ++w) {
                const int t = s_wbase[w][p];
                s_wbase[w][p] = run;
                run += t;
            }
        }
    }
    __syncthreads();

#pragma unroll
    for (int j = 0; j < 8; ++j) {
        const uint32_t bj = bytes[j];
        const uint32_t grp = __match_any_sync(FULL, bj);
        const int leader = __ffs(grp) - 1;
        int base = 0;
        if (bj && lane == leader)
            base = atomicAdd(&s_wbase[wid][bj], __popc(grp));
        base = __shfl_sync(FULL, base, leader);
        if (bj) {
            const int pos = base + __popc(grp & ((1u << lane) - 1u));
            s_idx[pos] = (uint16_t)(tid * 8 + j);
        }
    }
    __syncthreads();

    unsigned long long acc[T][2];
#pragma unroll
    for (int t = 0; t < T; ++t) { acc[t][0] = 0ull; acc[t][1] = 0ull; }

    const char* wbase = reinterpret_cast<const char*>(w2t) + tid * 16;
    const int nbins = s_nbins;

    for (int bi = 0; bi < nbins; ++bi) {
        const int p  = s_binlist[bi];
        const int st = s_start[p];
        const int en = st + s_cnt[p];

        unsigned long long rs0 = 0ull, rs1 = 0ull;
        for (int k = st; k < en; ++k) {
            const uint32_t i = s_idx[k];
            unsigned long long w01, w23;
            asm("ld.global.nc.L1::evict_last.v2.u64 {%0, %1}, [%2];"
                : "=l"(w01), "=l"(w23)
                : "l"(wbase + (size_t)i * (H1 * 4)));
            asm("add.rn.f32x2 %0, %0, %1;" : "+l"(rs0) : "l"(w01));
            asm("add.rn.f32x2 %0, %0, %1;" : "+l"(rs1) : "l"(w23));
        }

#pragma unroll
        for (int t = 0; t < T; ++t) {
            asm("{ .reg .pred q;\n\t"
                "setp.ne.u32 q, %4, 0;\n\t"
                "@q add.rn.f32x2 %0, %0, %2;\n\t"
                "@q add.rn.f32x2 %1, %1, %3; }"
                : "+l"(acc[t][0]), "+l"(acc[t][1])
                : "l"(rs0), "l"(rs1), "r"((unsigned)p & (1u << t)));
        }
    }

    const int n0 = tid * 4;
    const float4 b2v = *reinterpret_cast<const float4*>(b2 + n0);
    const float4 w3v = *reinterpret_cast<const float4*>(w3 + n0);
    float m0 = 0.0f, m1 = 0.0f, m2 = 0.0f, m3 = 0.0f, aout = 0.0f;
#pragma unroll
    for (int t = 0; t < T; ++t) {
        float a0, a1, a2, a3;
        asm("mov.b64 {%0, %1}, %2;" : "=f"(a0), "=f"(a1) : "l"(acc[t][0]));
        asm("mov.b64 {%0, %1}, %2;" : "=f"(a2), "=f"(a3) : "l"(acc[t][1]));
        const float c0 = a0 + b2v.x, c1 = a1 + b2v.y;
        const float c2 = a2 + b2v.z, c3 = a3 + b2v.w;
        const float r0 = (m0 > 1.0f) ? 1.0f : 0.0f;   // reset on OLD mem
        const float r1 = (m1 > 1.0f) ? 1.0f : 0.0f;
        const float r2 = (m2 > 1.0f) ? 1.0f : 0.0f;
        const float r3 = (m3 > 1.0f) ? 1.0f : 0.0f;
        m0 = 0.95f * m0 + c0 - r0;
        m1 = 0.95f * m1 + c1 - r1;
        m2 = 0.95f * m2 + c2 - r2;
        m3 = 0.95f * m3 + c3 - r3;
        aout += ((m0 - 1.0f) > 0.0f) ? w3v.x : 0.0f;
        aout += ((m1 - 1.0f) > 0.0f) ? w3v.y : 0.0f;
        aout += ((m2 - 1.0f) > 0.0f) ? w3v.z : 0.0f;
        aout += ((m3 - 1.0f) > 0.0f) ? w3v.w : 0.0f;
    }

#pragma unroll
    for (int d = 16; d > 0; d >>= 1)
        aout += __shfl_down_sync(FULL, aout, d);
    if (lane == 0) s_red[wid] = aout;
    __syncthreads();
    if (tid == 0) {
        out[b] = (s_red[0] + s_red[1] + s_red[2] + s_red[3]) * (1.0f / T)
               + __ldg(&b3[0]);
    }
}

// ---------------------------------------------------------------------------
extern "C" void kernel_launch(void* const* d_in, const int* in_sizes, int n_in,
                              void* d_out, int out_size)
{
    const float* data = (const float*)d_in[0];
    const float* w1   = (const float*)d_in[1];
    const float* b1   = (const float*)d_in[2];
    const float* w2   = (const float*)d_in[3];
    const float* b2   = (const float*)d_in[4];
    const float* w3   = (const float*)d_in[5];
    const float* b3   = (const float*)d_in[6];
    float* out = (float*)d_out;

    unsigned char* pack;
    float* w2t;
    cudaGetSymbolAddress((void**)&pack, g_pack);
    cudaGetSymbolAddress((void**)&w2t,  g_w2t);

    // 1) transpose w2 -> w2t [H0][H1]
    {
        dim3 grid(H0 / 32, H1 / 32);     // (32, 16)
        transpose_w2_kernel<<<grid, dim3(32, 8)>>>(w2, w2t);
    }

    // 2) GEMM1 (FFMA2) + fused LIF1 pack (cur1 never materialized)
    {
        dim3 grid(H0 / 128, BB / 128);   // (8, 128)
        sgemm1_pack_kernel<<<grid, 256>>>(data, w1, b1, pack, BB, H0, DIN);
    }

    // 3) fused sparse layer-2 + LIF2 + output head
    snn_tail_kernel<<<BB, 128>>>(pack, w2t, b2, w3, b3, out);
}